// round 13
// baseline (speedup 1.0000x reference)
#include <cuda_runtime.h>
#include <cstdint>

// out[b,c] = dot(x[b,c,:HW], weight[c,:HW]) + bias[c]
// B = 512, C = 512, HW = 784 (float32). HBM-streaming bound; traffic minimal.
// R13: stream x via ONE cp.async.bulk (6272 B aligned 2-row pair) into smem
// per block. The bulk engine issues 49 consecutive lines as a single ordered
// burst -> maximal DRAM row-buffer locality, no warp-jitter in the request
// stream. Compute reads x from smem; weight stays on the L1/__ldg path.

#define B_DIM 512
#define C_DIM 512
#define HW_DIM 784
#define HW_VEC4 (HW_DIM / 4)          // 196 float4 per row
#define PAIR_VEC4 (2 * HW_VEC4)       // 392 float4 per pair
#define PAIR_BYTES (PAIR_VEC4 * 16)   // 6272 B = 49 x 128B lines
#define TOTAL_ROWS (B_DIM * C_DIM)    // 262144

__global__ __launch_bounds__(64, 32) void scalar_mapping_kernel(
    const float* __restrict__ x,
    const float* __restrict__ weight,
    const float* __restrict__ bias,
    float* __restrict__ out)
{
    __shared__ alignas(128) float4 xs[PAIR_VEC4];   // 6272 B staging buffer
    __shared__ alignas(8) unsigned long long mbar;
    __shared__ float part[4];

    const int tid  = threadIdx.x;        // 0..63
    const int lane = tid & 31;
    const int wid  = tid >> 5;           // 0 or 1

    const int r0 = blockIdx.x * 2;       // even row
    const int c0 = r0 & (C_DIM - 1);     // even -> c1 = c0+1 never wraps
    const int c1 = c0 + 1;

    const float* __restrict__ xsrc = x + (size_t)r0 * HW_DIM;  // 128B-aligned
    const float4* __restrict__ w0 =
        reinterpret_cast<const float4*>(weight + (size_t)c0 * HW_DIM);
    const float4* __restrict__ w1 =
        reinterpret_cast<const float4*>(weight + (size_t)c1 * HW_DIM);

    // SMEM addresses for PTX
    uint32_t mbar_a, xs_a;
    asm("{ .reg .u64 t; cvta.to.shared.u64 t, %1; cvt.u32.u64 %0, t; }"
        : "=r"(mbar_a) : "l"(&mbar));
    asm("{ .reg .u64 t; cvta.to.shared.u64 t, %1; cvt.u32.u64 %0, t; }"
        : "=r"(xs_a) : "l"(xs));

    if (tid == 0)
        asm volatile("mbarrier.init.shared.b64 [%0], 1;" :: "r"(mbar_a) : "memory");
    __syncthreads();

    if (tid == 0) {
        asm volatile("mbarrier.arrive.expect_tx.shared.b64 _, [%0], %1;"
                     :: "r"(mbar_a), "r"((uint32_t)PAIR_BYTES) : "memory");
        asm volatile(
            "cp.async.bulk.shared::cta.global.mbarrier::complete_tx::bytes "
            "[%0], [%1], %2, [%3];"
            :: "r"(xs_a), "l"(xsrc), "r"((uint32_t)PAIR_BYTES), "r"(mbar_a)
            : "memory");
    }

    // Wait (acquire) for the bulk copy.
    {
        uint32_t done;
        asm volatile(
            "{\n\t.reg .pred p;\n\t"
            "mbarrier.try_wait.parity.acquire.cta.shared::cta.b64 p, [%1], 0;\n\t"
            "selp.b32 %0, 1, 0, p;\n\t}"
            : "=r"(done) : "r"(mbar_a) : "memory");
        if (!done) {
            asm volatile(
                "{\n\t.reg .pred P1;\n\t"
                "WL_%=:\n\t"
                "mbarrier.try_wait.parity.acquire.cta.shared::cta.b64 P1, [%0], 0, 0x989680;\n\t"
                "@P1 bra.uni WD_%=;\n\t"
                "bra.uni WL_%=;\n\t"
                "WD_%=:\n\t}"
                :: "r"(mbar_a) : "memory");
        }
    }

    float s0 = 0.0f, s1 = 0.0f;

    // 6 full iterations over [0, 384) + peeled tail (tid < 8).
    #pragma unroll
    for (int i = 0; i < 6; ++i) {
        const int f = tid + i * 64;
        const float4 xv = xs[f];                   // smem, conflict-free
        if (f < HW_VEC4) {
            const float4 wv = __ldg(&w0[f]);       // L1-resident weight
            s0 = fmaf(xv.x, wv.x, s0);
            s0 = fmaf(xv.y, wv.y, s0);
            s0 = fmaf(xv.z, wv.z, s0);
            s0 = fmaf(xv.w, wv.w, s0);
        } else {
            const float4 wv = __ldg(&w1[f - HW_VEC4]);
            s1 = fmaf(xv.x, wv.x, s1);
            s1 = fmaf(xv.y, wv.y, s1);
            s1 = fmaf(xv.z, wv.z, s1);
            s1 = fmaf(xv.w, wv.w, s1);
        }
    }
    if (tid < 8) {
        const int f = 384 + tid;
        const float4 xv = xs[f];
        const float4 wv = __ldg(&w1[f - HW_VEC4]);
        s1 = fmaf(xv.x, wv.x, s1);
        s1 = fmaf(xv.y, wv.y, s1);
        s1 = fmaf(xv.z, wv.z, s1);
        s1 = fmaf(xv.w, wv.w, s1);
    }

    #pragma unroll
    for (int off = 16; off > 0; off >>= 1) {
        s0 += __shfl_xor_sync(0xFFFFFFFFu, s0, off);
        s1 += __shfl_xor_sync(0xFFFFFFFFu, s1, off);
    }

    if (lane == 0) {
        part[wid * 2 + 0] = s0;
        part[wid * 2 + 1] = s1;
    }
    __syncthreads();

    if (tid == 0) {
        float2 o;
        o.x = part[0] + part[2] + __ldg(&bias[c0]);
        o.y = part[1] + part[3] + __ldg(&bias[c1]);
        *reinterpret_cast<float2*>(&out[r0]) = o;
    }
}

extern "C" void kernel_launch(void* const* d_in, const int* in_sizes, int n_in,
                              void* d_out, int out_size)
{
    const float* x      = (const float*)d_in[0];
    const float* weight = (const float*)d_in[1];
    const float* bias   = (const float*)d_in[2];
    float* out          = (float*)d_out;

    // One aligned 2-row pair per 64-thread block -> 131072 blocks in row order.
    const int blocks = TOTAL_ROWS / 2;

    scalar_mapping_kernel<<<blocks, 64>>>(x, weight, bias, out);
}

// round 15
// speedup vs baseline: 1.4875x; 1.4875x over previous
#include <cuda_runtime.h>
#include <cstdint>

// out[b,c] = dot(x[b,c,:HW], weight[c,:HW]) + bias[c]
// B = 512, C = 512, HW = 784 (float32). HBM-streaming bound; wall-clock is at
// ~7.2 TB/s (~90% of spec). R15 = R12 (aligned 2-row-pair 64-thr blocks, tail
// peeled, regs<=32, x via .cg L1-bypass) + L2::evict_first on x through the
// createpolicy/cache_hint form (the bare .L2::evict_first modifier is
// v8-only on this ptxas). Dead-on-arrival x lines leave L2 immediately,
// keeping the hot weight window stable.

#define B_DIM 512
#define C_DIM 512
#define HW_DIM 784
#define HW_VEC4 (HW_DIM / 4)          // 196 float4 per row
#define PAIR_VEC4 (2 * HW_VEC4)       // 392 float4 per row-pair
#define TOTAL_ROWS (B_DIM * C_DIM)    // 262144

// 128-bit load: L1-bypass (.cg) + L2 evict-first via cache-hint policy.
__device__ __forceinline__ float4 ldg128_stream(const float4* p, uint64_t pol) {
    float4 v;
    asm volatile(
        "ld.global.cg.L2::cache_hint.v4.f32 {%0,%1,%2,%3}, [%4], %5;"
        : "=f"(v.x), "=f"(v.y), "=f"(v.z), "=f"(v.w)
        : "l"(p), "l"(pol));
    return v;
}

__global__ __launch_bounds__(64, 32) void scalar_mapping_kernel(
    const float* __restrict__ x,
    const float* __restrict__ weight,
    const float* __restrict__ bias,
    float* __restrict__ out)
{
    __shared__ float part[4];   // {w0.s0, w0.s1, w1.s0, w1.s1}

    const int tid  = threadIdx.x;        // 0..63
    const int lane = tid & 31;
    const int wid  = tid >> 5;           // 0 or 1

    const int r0 = blockIdx.x * 2;       // even row
    const int c0 = r0 & (C_DIM - 1);     // even -> c1 = c0+1 never wraps
    const int c1 = c0 + 1;

    // L2 evict-first policy for the x stream (created once, reused).
    uint64_t pol;
    asm("createpolicy.fractional.L2::evict_first.b64 %0, 1.0;" : "=l"(pol));

    // Contiguous, 128B-aligned 2-row window of x (6272 B = 49 lines).
    const float4* __restrict__ xr =
        reinterpret_cast<const float4*>(x + (size_t)r0 * HW_DIM);
    const float4* __restrict__ w0 =
        reinterpret_cast<const float4*>(weight + (size_t)c0 * HW_DIM);
    const float4* __restrict__ w1 =
        reinterpret_cast<const float4*>(weight + (size_t)c1 * HW_DIM);

    float s0 = 0.0f, s1 = 0.0f;

    // 6 full iterations: f = tid + 64*i in [0, 384) -- predicate-free.
    #pragma unroll
    for (int i = 0; i < 6; ++i) {
        const int f = tid + i * 64;
        const float4 xv = ldg128_stream(&xr[f], pol);  // stream, L1-bypassed
        if (f < HW_VEC4) {
            const float4 wv = __ldg(&w0[f]);           // weight: L1/L2 resident
            s0 = fmaf(xv.x, wv.x, s0);
            s0 = fmaf(xv.y, wv.y, s0);
            s0 = fmaf(xv.z, wv.z, s0);
            s0 = fmaf(xv.w, wv.w, s0);
        } else {
            const float4 wv = __ldg(&w1[f - HW_VEC4]);
            s1 = fmaf(xv.x, wv.x, s1);
            s1 = fmaf(xv.y, wv.y, s1);
            s1 = fmaf(xv.z, wv.z, s1);
            s1 = fmaf(xv.w, wv.w, s1);
        }
    }
    // Peeled tail: f = 384 + tid, valid for tid < 8 (all in row 1).
    if (tid < 8) {
        const int f = 384 + tid;
        const float4 xv = ldg128_stream(&xr[f], pol);
        const float4 wv = __ldg(&w1[f - HW_VEC4]);
        s1 = fmaf(xv.x, wv.x, s1);
        s1 = fmaf(xv.y, wv.y, s1);
        s1 = fmaf(xv.z, wv.z, s1);
        s1 = fmaf(xv.w, wv.w, s1);
    }

    // Warp-level butterfly reduce of both accumulators.
    #pragma unroll
    for (int off = 16; off > 0; off >>= 1) {
        s0 += __shfl_xor_sync(0xFFFFFFFFu, s0, off);
        s1 += __shfl_xor_sync(0xFFFFFFFFu, s1, off);
    }

    if (lane == 0) {
        part[wid * 2 + 0] = s0;
        part[wid * 2 + 1] = s1;
    }
    __syncthreads();

    if (tid == 0) {
        float2 o;
        o.x = part[0] + part[2] + __ldg(&bias[c0]);
        o.y = part[1] + part[3] + __ldg(&bias[c1]);
        *reinterpret_cast<float2*>(&out[r0]) = o;   // 8B-aligned at even rows
    }
}

extern "C" void kernel_launch(void* const* d_in, const int* in_sizes, int n_in,
                              void* d_out, int out_size)
{
    const float* x      = (const float*)d_in[0];
    const float* weight = (const float*)d_in[1];
    const float* bias   = (const float*)d_in[2];
    float* out          = (float*)d_out;

    // One aligned 2-row pair per 64-thread block -> 131072 blocks in row order.
    const int blocks = TOTAL_ROWS / 2;

    scalar_mapping_kernel<<<blocks, 64>>>(x, weight, bias, out);
}

// round 16
// speedup vs baseline: 1.4907x; 1.0022x over previous
#include <cuda_runtime.h>
#include <cstdint>

// out[b,c] = dot(x[b,c,:HW], weight[c,:HW]) + bias[c]
// B = 512, C = 512, HW = 784 (float32). HBM-streaming bound; traffic is
// provably minimal (828 MB = x once + out). FINAL configuration (R12 shape,
// confirmed best at 115.2 us = ~7.2 TB/s wall, ~90% of HBM spec):
//  - aligned 2-row pairs (6272 B = exactly 49 x 128B lines) per 64-thr block
//  - x via ld.global.cg (L1 bypass; zero reuse) -- L1 reserved for weight
//  - weight via __ldg (L1/L2 resident, reused every 256 blocks per SM)
//  - peeled tail: 6 predicate-free full iterations + 8-thread tail
//  - __launch_bounds__(64, 32): regs<=32, full 64 warps/SM RF fit
//  - row-ordered grid: sequential DRAM window across the resident wave
// Probed and rejected: grid-stride (R2), front-batching (R3), smem weight
// tiling (R4), 1-warp CTAs (R7), seq row-pairs (R8), v8 loads (R11),
// cp.async.bulk (R13), L2::evict_first (R15).

#define B_DIM 512
#define C_DIM 512
#define HW_DIM 784
#define HW_VEC4 (HW_DIM / 4)          // 196 float4 per row
#define PAIR_VEC4 (2 * HW_VEC4)       // 392 float4 per row-pair
#define TOTAL_ROWS (B_DIM * C_DIM)    // 262144

// 128-bit load, L1-bypass (cache-global: L2 only)
__device__ __forceinline__ float4 ldg128_cg(const float4* p) {
    float4 v;
    asm volatile("ld.global.cg.v4.f32 {%0,%1,%2,%3}, [%4];"
                 : "=f"(v.x), "=f"(v.y), "=f"(v.z), "=f"(v.w)
                 : "l"(p));
    return v;
}

__global__ __launch_bounds__(64, 32) void scalar_mapping_kernel(
    const float* __restrict__ x,
    const float* __restrict__ weight,
    const float* __restrict__ bias,
    float* __restrict__ out)
{
    __shared__ float part[4];   // {w0.s0, w0.s1, w1.s0, w1.s1}

    const int tid  = threadIdx.x;        // 0..63
    const int lane = tid & 31;
    const int wid  = tid >> 5;           // 0 or 1

    const int r0 = blockIdx.x * 2;       // even row
    const int c0 = r0 & (C_DIM - 1);     // even -> c1 = c0+1 never wraps
    const int c1 = c0 + 1;

    // Contiguous, 128B-aligned 2-row window of x (6272 B = 49 lines).
    const float4* __restrict__ xr =
        reinterpret_cast<const float4*>(x + (size_t)r0 * HW_DIM);
    const float4* __restrict__ w0 =
        reinterpret_cast<const float4*>(weight + (size_t)c0 * HW_DIM);
    const float4* __restrict__ w1 =
        reinterpret_cast<const float4*>(weight + (size_t)c1 * HW_DIM);

    float s0 = 0.0f, s1 = 0.0f;

    // 6 full iterations: f = tid + 64*i in [0, 384) -- predicate-free.
    #pragma unroll
    for (int i = 0; i < 6; ++i) {
        const int f = tid + i * 64;
        const float4 xv = ldg128_cg(&xr[f]);       // DRAM stream, L1-bypassed
        if (f < HW_VEC4) {
            const float4 wv = __ldg(&w0[f]);       // L1-resident weight
            s0 = fmaf(xv.x, wv.x, s0);
            s0 = fmaf(xv.y, wv.y, s0);
            s0 = fmaf(xv.z, wv.z, s0);
            s0 = fmaf(xv.w, wv.w, s0);
        } else {
            const float4 wv = __ldg(&w1[f - HW_VEC4]);
            s1 = fmaf(xv.x, wv.x, s1);
            s1 = fmaf(xv.y, wv.y, s1);
            s1 = fmaf(xv.z, wv.z, s1);
            s1 = fmaf(xv.w, wv.w, s1);
        }
    }
    // Peeled tail: f = 384 + tid, valid for tid < 8 (all in row 1).
    if (tid < 8) {
        const int f = 384 + tid;
        const float4 xv = ldg128_cg(&xr[f]);
        const float4 wv = __ldg(&w1[f - HW_VEC4]);
        s1 = fmaf(xv.x, wv.x, s1);
        s1 = fmaf(xv.y, wv.y, s1);
        s1 = fmaf(xv.z, wv.z, s1);
        s1 = fmaf(xv.w, wv.w, s1);
    }

    // Warp-level butterfly reduce of both accumulators.
    #pragma unroll
    for (int off = 16; off > 0; off >>= 1) {
        s0 += __shfl_xor_sync(0xFFFFFFFFu, s0, off);
        s1 += __shfl_xor_sync(0xFFFFFFFFu, s1, off);
    }

    if (lane == 0) {
        part[wid * 2 + 0] = s0;
        part[wid * 2 + 1] = s1;
    }
    __syncthreads();

    if (tid == 0) {
        float2 o;
        o.x = part[0] + part[2] + __ldg(&bias[c0]);
        o.y = part[1] + part[3] + __ldg(&bias[c1]);
        *reinterpret_cast<float2*>(&out[r0]) = o;   // 8B-aligned at even rows
    }
}

extern "C" void kernel_launch(void* const* d_in, const int* in_sizes, int n_in,
                              void* d_out, int out_size)
{
    const float* x      = (const float*)d_in[0];
    const float* weight = (const float*)d_in[1];
    const float* bias   = (const float*)d_in[2];
    float* out          = (float*)d_out;

    // One aligned 2-row pair per 64-thread block -> 131072 blocks in row order.
    const int blocks = TOTAL_ROWS / 2;

    scalar_mapping_kernel<<<blocks, 64>>>(x, weight, bias, out);
}